// round 8
// baseline (speedup 1.0000x reference)
#include <cuda_runtime.h>
#include <cstdint>
#include <cstddef>

#define BB   256
#define CH   64
#define HH   28
#define WW   28
#define HW   784
#define H2   14
#define W2   14
#define P2   196
#define NC   128
#define FP   60        // fwd filter pitch (strip-of-8 layout)
#define CP   52        // inv filter pitch (strip-of-4 layout, pad 9)
#define TP   197       // mix tile pitch: 197 % 32 = 5 -> conflict-free both ways
#define MIX_SMEM_BYTES 225600

__device__ constexpr float kH0[13] = {
    -0.0017578f, 0.0f, 0.0222656f, -0.046875f, -0.0482422f, 0.296875f,
     0.5554688f, 0.296875f, -0.0482422f, -0.046875f, 0.0222656f, 0.0f, -0.0017578f};
__device__ constexpr float kH1[19] = {
    -7.06e-05f, 0.0f, 0.0013419f, -0.0018834f, -0.0071568f, 0.023856f,
     0.0556431f, -0.0516881f, -0.2997576f, 0.5594308f, -0.2997576f, -0.0516881f,
     0.0556431f, 0.023856f, -0.0071568f, -0.0018834f, 0.0013419f, 0.0f, -7.06e-05f};
__device__ constexpr float kG0[19] = {
     7.06e-05f, 0.0f, -0.0013419f, -0.0018834f, 0.0071568f, 0.023856f,
    -0.0556431f, -0.0516881f, 0.2997576f, 0.5594308f, 0.2997576f, -0.0516881f,
    -0.0556431f, 0.023856f, 0.0071568f, -0.0018834f, -0.0013419f, 0.0f, 7.06e-05f};
__device__ constexpr float kG1[13] = {
     0.0017578f, 0.0f, -0.0222656f, -0.046875f, 0.0482422f, 0.296875f,
    -0.5554688f, 0.296875f, 0.0482422f, -0.046875f, -0.0222656f, 0.0f, 0.0017578f};

#define INV_SQRT2 0.70710678118654752440f

// scratch (allocation-free: __device__ globals)
__device__ float g_img[(size_t)BB * CH * HW];
__device__ float g_ll [(size_t)BB * CH * HW];
__device__ float g_xh [2][(size_t)BB * CH * 6 * P2];   // [ri][b][c][s][p]

// packed complex weights: quad = {wr, wi, -wi, wr}
__device__ float4 g_cwq4[2][1024];
__device__ float4 g_twq4[2][2744];
__device__ float2 g_cbq [2][64];
__device__ float2 g_tbq [2][196];

typedef unsigned long long u64;

__device__ __forceinline__ u64 pk2(float lo, float hi) {
    u64 r; asm("mov.b64 %0, {%1, %2};" : "=l"(r) : "f"(lo), "f"(hi)); return r;
}
__device__ __forceinline__ void upk2(u64 v, float& lo, float& hi) {
    asm("mov.b64 {%0, %1}, %2;" : "=f"(lo), "=f"(hi) : "l"(v));
}
__device__ __forceinline__ void ffma2(u64& a, u64 x, u64 w) {
    asm("fma.rn.f32x2 %0, %1, %2, %0;" : "+l"(a) : "l"(x), "l"(w));
}
__device__ __forceinline__ void lds2u64(u64& a, u64& b, unsigned addr) {
    asm volatile("ld.shared.v2.u64 {%0, %1}, [%2];" : "=l"(a), "=l"(b) : "r"(addr));
}
__device__ __forceinline__ u64 lds1u64(unsigned addr) {
    u64 r; asm volatile("ld.shared.u64 %0, [%1];" : "=l"(r) : "r"(addr)); return r;
}

// ---------------- K_pack ----------------
__global__ void k_pack(const float* __restrict__ w_lh1, const float* __restrict__ w_lh2,
                       const float* __restrict__ b_lh1, const float* __restrict__ b_lh2,
                       const float* __restrict__ w_t1,  const float* __restrict__ w_t2,
                       const float* __restrict__ b_t1,  const float* __restrict__ b_t2) {
    int i = blockIdx.x * 256 + threadIdx.x;
    if (i < 1024) {
        int n = i >> 8, k = (i >> 4) & 15, d = i & 15;
        int src = n * 256 + d * 16 + k;
        float wr1 = w_lh1[src], wi1 = w_lh1[1024 + src];
        g_cwq4[0][i] = make_float4(wr1, wi1, -wi1, wr1);
        float wr2 = w_lh2[src], wi2 = w_lh2[1024 + src];
        g_cwq4[1][i] = make_float4(wr2, wi2, -wi2, wr2);
    }
    if (i < 2744) {
        int h2 = i / 196, rem = i % 196;
        int k = rem / 14, d = rem % 14;
        int src = (h2 * 14 + d) * 14 + k;
        float wr1 = w_t1[src], wi1 = w_t1[2744 + src];
        g_twq4[0][i] = make_float4(wr1, wi1, -wi1, wr1);
        float wr2 = w_t2[src], wi2 = w_t2[2744 + src];
        g_twq4[1][i] = make_float4(wr2, wi2, -wi2, wr2);
    }
    if (i < 64) {
        g_cbq[0][i] = make_float2(b_lh1[i], b_lh1[64 + i]);
        g_cbq[1][i] = make_float2(b_lh2[i], b_lh2[64 + i]);
    }
    if (i < 196) {
        g_tbq[0][i] = make_float2(b_t1[i], b_t1[196 + i]);
        g_tbq[1][i] = make_float2(b_t2[i], b_t2[196 + i]);
    }
}

// ---------------- K0: transpose x[:, :, 64:128] -> g_img[b][c][hw] ----------------
__global__ void k_transpose_in(const float* __restrict__ x) {
    __shared__ float t[56][65];
    int b   = blockIdx.x / 14;
    int hw0 = (blockIdx.x % 14) * 56;
    #pragma unroll
    for (int it = 0; it < 14; ++it) {
        int idx = it * 256 + threadIdx.x;
        int i = idx >> 6, c = idx & 63;
        t[i][c] = x[((size_t)b * HW + hw0 + i) * NC + CH + c];
    }
    __syncthreads();
    #pragma unroll
    for (int it = 0; it < 14; ++it) {
        int idx = it * 256 + threadIdx.x;
        int i = idx % 56, c = idx / 56;
        g_img[((size_t)b * CH + c) * HW + hw0 + i] = t[i][c];
    }
}

// ---------------- K1: depthwise 3x3 conv ----------------
__global__ void k_dwconv(const float* __restrict__ x, const float* __restrict__ w,
                         const float* __restrict__ bias, float* __restrict__ out) {
    int tid   = threadIdx.x;
    int c     = tid & 63;
    int local = tid >> 6;
    long long base = (long long)blockIdx.x * 4 + local;
    int b  = (int)(base / HW);
    int hw = (int)(base % HW);
    int h  = hw / WW, wc = hw % WW;
    float wr[9];
    #pragma unroll
    for (int j = 0; j < 9; ++j) wr[j] = w[c * 9 + j];
    float acc = bias[c];
    #pragma unroll
    for (int dh = -1; dh <= 1; ++dh) {
        int hh = h + dh;
        if (hh < 0 || hh >= HH) continue;
        #pragma unroll
        for (int dw = -1; dw <= 1; ++dw) {
            int ww2 = wc + dw;
            if (ww2 < 0 || ww2 >= WW) continue;
            acc += x[((size_t)b * HW + hh * WW + ww2) * NC + c] * wr[(dh + 1) * 3 + (dw + 1)];
        }
    }
    out[((size_t)b * HW + hw) * NC + c] = acc;
}

// ---------------- K2: forward DTCWT (warp strip-of-8) ----------------
__global__ void __launch_bounds__(128, 7) k_fwd(const float* __restrict__ w_ll) {
    __shared__ __align__(16) float sAp [HH][FP];     // [h][12+w]
    __shared__ __align__(16) float sLoT[WW][FP];     // [w][12+h]
    __shared__ __align__(16) float sHiT[WW][FP];
    __shared__ float sLH[HW], sHL[HW], sHH[HW];

    int bid = blockIdx.x;              // b*64 + c
    int c   = bid & 63;
    int tid = threadIdx.x;
    int ws  = tid >> 5, l = tid & 31;

    for (int i = tid; i < 196; i += 128) {
        float4 v = *(const float4*)(g_img + (size_t)bid * HW + i * 4);
        int h = (i * 4) / 28, w = (i * 4) % 28;
        *(float4*)&sAp[h][12 + w] = v;
    }
    __syncthreads();
    for (int i = tid; i < 28 * 9; i += 128) {
        int h = i / 9, j = i % 9;
        sAp[h][11 - j] = sAp[h][12 + j];
        sAp[h][40 + j] = sAp[h][39 - j];
    }
    __syncthreads();

    if (l < 28) {
        int h = l, w0 = ws * 8;
        float X[32];
        #pragma unroll
        for (int q = 0; q < 8; ++q)
            *(float4*)&X[q * 4] = *(const float4*)&sAp[h][w0 + q * 4];
        #pragma unroll
        for (int t = 0; t < 8; ++t) {
            float hi = 0.f, lo = 0.f;
            #pragma unroll
            for (int j = 0; j < 19; ++j) hi = fmaf(X[3 + t + j], kH1[j], hi);
            #pragma unroll
            for (int j = 0; j < 13; ++j) lo = fmaf(X[6 + t + j], kH0[j], lo);
            if (w0 + t < 28) {
                sLoT[w0 + t][12 + h] = lo;
                sHiT[w0 + t][12 + h] = hi;
            }
        }
    }
    __syncthreads();
    for (int i = tid; i < 28 * 9; i += 128) {
        int w = i / 9, j = i % 9;
        sLoT[w][11 - j] = sLoT[w][12 + j];  sLoT[w][40 + j] = sLoT[w][39 - j];
        sHiT[w][11 - j] = sHiT[w][12 + j];  sHiT[w][40 + j] = sHiT[w][39 - j];
    }
    __syncthreads();

    if (l < 28) {
        int w = l, h0 = ws * 8;
        float ll[8], lh[8];
        {
            float Y[32];
            #pragma unroll
            for (int q = 0; q < 8; ++q)
                *(float4*)&Y[q * 4] = *(const float4*)&sLoT[w][h0 + q * 4];
            #pragma unroll
            for (int t = 0; t < 8; ++t) {
                float a = 0.f, b2 = 0.f;
                #pragma unroll
                for (int j = 0; j < 13; ++j) a = fmaf(Y[6 + t + j], kH0[j], a);
                #pragma unroll
                for (int j = 0; j < 19; ++j) b2 = fmaf(Y[3 + t + j], kH1[j], b2);
                ll[t] = a; lh[t] = b2;
            }
        }
        float hl[8], hh[8];
        {
            float Z[32];
            #pragma unroll
            for (int q = 0; q < 8; ++q)
                *(float4*)&Z[q * 4] = *(const float4*)&sHiT[w][h0 + q * 4];
            #pragma unroll
            for (int t = 0; t < 8; ++t) {
                float a = 0.f, b2 = 0.f;
                #pragma unroll
                for (int j = 0; j < 13; ++j) a = fmaf(Z[6 + t + j], kH0[j], a);
                #pragma unroll
                for (int j = 0; j < 19; ++j) b2 = fmaf(Z[3 + t + j], kH1[j], b2);
                hl[t] = a; hh[t] = b2;
            }
        }
        #pragma unroll
        for (int t = 0; t < 8; ++t) {
            if (h0 + t < 28) {
                int pos = (h0 + t) * 28 + w;
                g_ll[(size_t)bid * HW + pos] = ll[t] * w_ll[c * HW + pos];
                sLH[pos] = lh[t]; sHL[pos] = hl[t]; sHH[pos] = hh[t];
            }
        }
    }
    __syncthreads();

    for (int p = tid; p < 196; p += 128) {
        int h2 = p / 14, w2 = p - h2 * 14;
        int o  = (2 * h2) * WW + 2 * w2;
        #pragma unroll
        for (int band = 0; band < 3; ++band) {
            const float* src = (band == 0) ? sLH : (band == 1) ? sHH : sHL;
            int sp = (band == 0) ? 0 : (band == 1) ? 1 : 2;
            int sq = (band == 0) ? 5 : (band == 1) ? 4 : 3;
            float a  = src[o]          * INV_SQRT2;
            float bb = src[o + 1]      * INV_SQRT2;
            float cc = src[o + WW]     * INV_SQRT2;
            float dd = src[o + WW + 1] * INV_SQRT2;
            size_t bp = ((size_t)bid * 6 + sp) * P2 + p;
            size_t bq = ((size_t)bid * 6 + sq) * P2 + p;
            g_xh[0][bp] = a - dd;
            g_xh[1][bp] = bb + cc;
            g_xh[0][bq] = a + dd;
            g_xh[1][bq] = bb - cc;
        }
    }
}

// ---------------- K3: fused channel + token mixing per (b, s) ----------------
// smem: tile Tr/Ti [64][197] + all packed weights (225,600 B total)
__global__ void __launch_bounds__(256, 1) k_mix2() {
    extern __shared__ float sm[];
    float*  Tr  = sm;                       // [64][TP]
    float*  Ti  = sm + 64 * TP;
    float4* scw = (float4*)(sm + 25216);    // [2][1024]
    float2* scb = (float2*)(sm + 33408);    // [2][64]
    float4* stw = (float4*)(sm + 33664);    // [2][2744]
    float2* stb = (float2*)(sm + 55616);    // [2][196]

    int tid = threadIdx.x;
    int b = blockIdx.x / 6, s = blockIdx.x % 6;

    const float4* gcw = &g_cwq4[0][0];
    for (int i = tid; i < 2048; i += 256) scw[i] = gcw[i];
    const float2* gcb = &g_cbq[0][0];
    if (tid < 128) scb[tid] = gcb[tid];
    const float4* gtw = &g_twq4[0][0];
    for (int i = tid; i < 5488; i += 256) stw[i] = gtw[i];
    const float2* gtb = &g_tbq[0][0];
    for (int i = tid; i < 392; i += 256) stb[i] = gtb[i];

    size_t gbase = ((size_t)b * 384 + s) * 196;
    for (int i = tid; i < 64 * 196; i += 256) {
        int c = i / 196, p = i - c * 196;
        Tr[c * TP + p] = g_xh[0][gbase + (size_t)c * 1176 + p];
        Ti[c * TP + p] = g_xh[1][gbase + (size_t)c * 1176 + p];
    }
    __syncthreads();

    // ---- channel mixing (thread = position) ----
    unsigned w0a = (unsigned)__cvta_generic_to_shared(scw);
    unsigned w1a = w0a + 1024 * 16;
    unsigned b0a = (unsigned)__cvta_generic_to_shared(scb);
    unsigned b1a = b0a + 64 * 8;

    if (tid < 196) {
        int p = tid;
        for (int n = 0; n < 4; ++n) {
            u64 Xp[16], Xq[16];
            #pragma unroll
            for (int d = 0; d < 16; ++d) {
                float r = Tr[(n * 16 + d) * TP + p];
                float m = Ti[(n * 16 + d) * TP + p];
                Xp[d] = pk2(r, r); Xq[d] = pk2(m, m);
            }
            float mr[16], mi[16];
            #pragma unroll
            for (int k = 0; k < 16; ++k) {
                u64 A = lds1u64(b0a + (unsigned)(n * 16 + k) * 8);
                unsigned wa = w0a + (unsigned)((n * 16 + k) * 16) * 16;
                #pragma unroll
                for (int d = 0; d < 16; ++d) {
                    u64 W0, W1; lds2u64(W0, W1, wa + d * 16);
                    ffma2(A, Xp[d], W0);
                    ffma2(A, Xq[d], W1);
                }
                float ar, ai; upk2(A, ar, ai);
                mr[k] = fmaxf(ar, 0.f);
                mi[k] = fmaxf(ai, 0.f);
            }
            #pragma unroll
            for (int d = 0; d < 16; ++d) { Xp[d] = pk2(mr[d], mr[d]); Xq[d] = pk2(mi[d], mi[d]); }
            #pragma unroll
            for (int k = 0; k < 16; ++k) {
                u64 A = lds1u64(b1a + (unsigned)(n * 16 + k) * 8);
                unsigned wa = w1a + (unsigned)((n * 16 + k) * 16) * 16;
                #pragma unroll
                for (int d = 0; d < 16; ++d) {
                    u64 W0, W1; lds2u64(W0, W1, wa + d * 16);
                    ffma2(A, Xp[d], W0);
                    ffma2(A, Xq[d], W1);
                }
                float ar, ai; upk2(A, ar, ai);
                Tr[(n * 16 + k) * TP + p] = ar;
                Ti[(n * 16 + k) * TP + p] = ai;
            }
        }
    }
    __syncthreads();

    // ---- token mixing (warp-task = (h2, c-half); lane = channel) ----
    unsigned tw0 = (unsigned)__cvta_generic_to_shared(stw);
    unsigned tw1 = tw0 + 2744 * 16;
    unsigned tb0 = (unsigned)__cvta_generic_to_shared(stb);
    unsigned tb1 = tb0 + 196 * 8;
    int warp = tid >> 5, lane = tid & 31;
    for (int task = warp; task < 28; task += 8) {
        int h2 = task >> 1;
        int c  = (task & 1) * 32 + lane;
        float* Rr = Tr + c * TP + h2 * 14;
        float* Ri = Ti + c * TP + h2 * 14;
        u64 Xp[14], Xq[14];
        #pragma unroll
        for (int d = 0; d < 14; ++d) {
            float r = Rr[d], m = Ri[d];
            Xp[d] = pk2(r, r); Xq[d] = pk2(m, m);
        }
        float mr[14], mi[14];
        #pragma unroll
        for (int k = 0; k < 14; ++k) {
            u64 A = lds1u64(tb0 + (unsigned)(h2 * 14 + k) * 8);
            unsigned wa = tw0 + (unsigned)(h2 * 196 + k * 14) * 16;
            #pragma unroll
            for (int d = 0; d < 14; ++d) {
                u64 W0, W1; lds2u64(W0, W1, wa + d * 16);
                ffma2(A, Xp[d], W0);
                ffma2(A, Xq[d], W1);
            }
            float ar, ai; upk2(A, ar, ai);
            mr[k] = fmaxf(ar, 0.f);
            mi[k] = fmaxf(ai, 0.f);
        }
        #pragma unroll
        for (int d = 0; d < 14; ++d) { Xp[d] = pk2(mr[d], mr[d]); Xq[d] = pk2(mi[d], mi[d]); }
        #pragma unroll
        for (int k = 0; k < 14; ++k) {
            u64 A = lds1u64(tb1 + (unsigned)(h2 * 14 + k) * 8);
            unsigned wa = tw1 + (unsigned)(h2 * 196 + k * 14) * 16;
            #pragma unroll
            for (int d = 0; d < 14; ++d) {
                u64 W0, W1; lds2u64(W0, W1, wa + d * 16);
                ffma2(A, Xp[d], W0);
                ffma2(A, Xq[d], W1);
            }
            float ar, ai; upk2(A, ar, ai);
            Rr[k] = ar; Ri[k] = ai;
        }
    }
    __syncthreads();

    for (int i = tid; i < 64 * 196; i += 256) {
        int c = i / 196, p = i - c * 196;
        g_xh[0][gbase + (size_t)c * 1176 + p] = Tr[c * TP + p];
        g_xh[1][gbase + (size_t)c * 1176 + p] = Ti[c * TP + p];
    }
}

// ---------------- K4: inverse DTCWT (strip-of-4, pad-9, R5-best) ----------------
__global__ void __launch_bounds__(224, 2) k_inv() {
    __shared__ float sLLT[WW][CP];     // transposed padded (pad in h)
    __shared__ float sLHT[WW][CP];
    __shared__ float sHLT[WW][CP];
    __shared__ float sHHT[WW][CP];
    __shared__ float sLo [HH][CP];     // row-major padded (pad in w)
    __shared__ float sHi [HH][CP];

    int bid = blockIdx.x;
    int tid = threadIdx.x;

    if (tid < 196) {
        float4 v = *(const float4*)(g_ll + (size_t)bid * HW + tid * 4);
        int h = (tid * 4) / 28, w = (tid * 4) % 28;
        sLLT[w][9 + h]     = v.x;
        sLLT[w + 1][9 + h] = v.y;
        sLLT[w + 2][9 + h] = v.z;
        sLLT[w + 3][9 + h] = v.w;
    }

    if (tid < 196) {   // c2q -> transposed arrays
        int p = tid, h2 = p / 14, w2 = p - h2 * 14;
        size_t base = (size_t)bid * 6 * P2;
        int hr = 9 + 2 * h2, wc = 2 * w2;
        #pragma unroll
        for (int band = 0; band < 3; ++band) {
            int sa = (band == 0) ? 0 : (band == 1) ? 2 : 1;   // lh:(0,5) hl:(2,3) hh:(1,4)
            int sb = (band == 0) ? 5 : (band == 1) ? 3 : 4;
            float ra = g_xh[0][base + sa * P2 + p], ia = g_xh[1][base + sa * P2 + p];
            float rb = g_xh[0][base + sb * P2 + p], ib = g_xh[1][base + sb * P2 + p];
            float (*dst)[CP] = (band == 0) ? sLHT : (band == 1) ? sHLT : sHHT;
            dst[wc][hr]         = (ra + rb) * INV_SQRT2;
            dst[wc + 1][hr]     = (ia + ib) * INV_SQRT2;
            dst[wc][hr + 1]     = (ia - ib) * INV_SQRT2;
            dst[wc + 1][hr + 1] = (rb - ra) * INV_SQRT2;
        }
    }
    __syncthreads();
    for (int i = tid; i < 28 * 9; i += 224) {
        int w = i / 9, j = i % 9;
        sLLT[w][8 - j] = sLLT[w][9 + j];  sLLT[w][37 + j] = sLLT[w][36 - j];
        sLHT[w][8 - j] = sLHT[w][9 + j];  sLHT[w][37 + j] = sLHT[w][36 - j];
        sHLT[w][8 - j] = sHLT[w][9 + j];  sHLT[w][37 + j] = sHLT[w][36 - j];
        sHHT[w][8 - j] = sHHT[w][9 + j];  sHHT[w][37 + j] = sHHT[w][36 - j];
    }
    __syncthreads();

    if (tid < 196) {
        int w = tid % 28, h0 = (tid / 28) * 4;
        {
            float A[22], B[22];
            #pragma unroll
            for (int j = 0; j < 22; ++j) A[j] = sLLT[w][h0 + j];
            #pragma unroll
            for (int j = 0; j < 22; ++j) B[j] = sLHT[w][h0 + j];
            #pragma unroll
            for (int t = 0; t < 4; ++t) {
                float lo = 0.f;
                #pragma unroll
                for (int j = 0; j < 19; ++j) lo = fmaf(A[t + j], kG0[j], lo);
                #pragma unroll
                for (int j = 0; j < 13; ++j) lo = fmaf(B[t + 3 + j], kG1[j], lo);
                sLo[h0 + t][9 + w] = lo;
            }
        }
        {
            float A[22], B[22];
            #pragma unroll
            for (int j = 0; j < 22; ++j) A[j] = sHLT[w][h0 + j];
            #pragma unroll
            for (int j = 0; j < 22; ++j) B[j] = sHHT[w][h0 + j];
            #pragma unroll
            for (int t = 0; t < 4; ++t) {
                float hi = 0.f;
                #pragma unroll
                for (int j = 0; j < 19; ++j) hi = fmaf(A[t + j], kG0[j], hi);
                #pragma unroll
                for (int j = 0; j < 13; ++j) hi = fmaf(B[t + 3 + j], kG1[j], hi);
                sHi[h0 + t][9 + w] = hi;
            }
        }
    }
    __syncthreads();
    for (int i = tid; i < 28 * 9; i += 224) {
        int h = i / 9, j = i % 9;
        sLo[h][8 - j] = sLo[h][9 + j];  sLo[h][37 + j] = sLo[h][36 - j];
        sHi[h][8 - j] = sHi[h][9 + j];  sHi[h][37 + j] = sHi[h][36 - j];
    }
    __syncthreads();

    if (tid < 196) {
        int h = tid % 28, w0 = (tid / 28) * 4;
        float X[22], Y[22];
        #pragma unroll
        for (int j = 0; j < 22; ++j) X[j] = sLo[h][w0 + j];
        #pragma unroll
        for (int j = 0; j < 22; ++j) Y[j] = sHi[h][w0 + j];
        float4 v;
        float o[4];
        #pragma unroll
        for (int t = 0; t < 4; ++t) {
            float r = 0.f;
            #pragma unroll
            for (int j = 0; j < 19; ++j) r = fmaf(X[t + j], kG0[j], r);
            #pragma unroll
            for (int j = 0; j < 13; ++j) r = fmaf(Y[t + 3 + j], kG1[j], r);
            o[t] = r;
        }
        v.x = o[0]; v.y = o[1]; v.z = o[2]; v.w = o[3];
        *(float4*)(g_img + (size_t)bid * HW + h * 28 + w0) = v;
    }
}

// ---------------- K5: transpose g_img -> out[:, :, 64:128] ----------------
__global__ void k_transpose_out(float* __restrict__ out) {
    __shared__ float t[56][65];
    int b   = blockIdx.x / 14;
    int hw0 = (blockIdx.x % 14) * 56;
    #pragma unroll
    for (int it = 0; it < 14; ++it) {
        int idx = it * 256 + threadIdx.x;
        int i = idx % 56, c = idx / 56;
        t[i][c] = g_img[((size_t)b * CH + c) * HW + hw0 + i];
    }
    __syncthreads();
    #pragma unroll
    for (int it = 0; it < 14; ++it) {
        int idx = it * 256 + threadIdx.x;
        int i = idx >> 6, c = idx & 63;
        out[((size_t)b * HW + hw0 + i) * NC + CH + c] = t[i][c];
    }
}

extern "C" void kernel_launch(void* const* d_in, const int* in_sizes, int n_in,
                              void* d_out, int out_size) {
    const float* x      = (const float*)d_in[0];
    const float* conv_w = (const float*)d_in[1];
    const float* conv_b = (const float*)d_in[2];
    const float* w_ll   = (const float*)d_in[3];
    const float* w_lh1  = (const float*)d_in[4];
    const float* w_lh2  = (const float*)d_in[5];
    const float* b_lh1  = (const float*)d_in[6];
    const float* b_lh2  = (const float*)d_in[7];
    const float* w_t1   = (const float*)d_in[8];
    const float* w_t2   = (const float*)d_in[9];
    const float* b_t1   = (const float*)d_in[10];
    const float* b_t2   = (const float*)d_in[11];
    float* out = (float*)d_out;

    cudaFuncSetAttribute(k_mix2, cudaFuncAttributeMaxDynamicSharedMemorySize,
                         MIX_SMEM_BYTES);

    k_pack<<<11, 256>>>(w_lh1, w_lh2, b_lh1, b_lh2, w_t1, w_t2, b_t1, b_t2);
    k_transpose_in<<<BB * 14, 256>>>(x);
    k_dwconv<<<BB * HW / 4, 256>>>(x, conv_w, conv_b, out);
    k_fwd<<<BB * CH, 128>>>(w_ll);
    k_mix2<<<BB * 6, 256, MIX_SMEM_BYTES>>>();
    k_inv<<<BB * CH, 224>>>();
    k_transpose_out<<<BB * 14, 256>>>(out);
}

// round 9
// speedup vs baseline: 1.8724x; 1.8724x over previous
#include <cuda_runtime.h>
#include <cstdint>
#include <cstddef>

#define BB   256
#define CH   64
#define HH   28
#define WW   28
#define HW   784
#define H2   14
#define W2   14
#define P2   196
#define NC   128
#define FP   60        // fwd filter pitch (strip-of-8 layout)
#define CP   52        // inv filter pitch (strip-of-4 layout, pad 9)

__device__ constexpr float kH0[13] = {
    -0.0017578f, 0.0f, 0.0222656f, -0.046875f, -0.0482422f, 0.296875f,
     0.5554688f, 0.296875f, -0.0482422f, -0.046875f, 0.0222656f, 0.0f, -0.0017578f};
__device__ constexpr float kH1[19] = {
    -7.06e-05f, 0.0f, 0.0013419f, -0.0018834f, -0.0071568f, 0.023856f,
     0.0556431f, -0.0516881f, -0.2997576f, 0.5594308f, -0.2997576f, -0.0516881f,
     0.0556431f, 0.023856f, -0.0071568f, -0.0018834f, 0.0013419f, 0.0f, -7.06e-05f};
__device__ constexpr float kG0[19] = {
     7.06e-05f, 0.0f, -0.0013419f, -0.0018834f, 0.0071568f, 0.023856f,
    -0.0556431f, -0.0516881f, 0.2997576f, 0.5594308f, 0.2997576f, -0.0516881f,
    -0.0556431f, 0.023856f, 0.0071568f, -0.0018834f, -0.0013419f, 0.0f, 7.06e-05f};
__device__ constexpr float kG1[13] = {
     0.0017578f, 0.0f, -0.0222656f, -0.046875f, 0.0482422f, 0.296875f,
    -0.5554688f, 0.296875f, 0.0482422f, -0.046875f, -0.0222656f, 0.0f, 0.0017578f};

#define INV_SQRT2 0.70710678118654752440f

// scratch (allocation-free: __device__ globals)
__device__ float g_img[(size_t)BB * CH * HW];
__device__ float g_ll [(size_t)BB * CH * HW];
__device__ float g_xh [2][(size_t)BB * CH * 6 * P2];   // [ri][b][c][s][p]

// packed complex weights: quad = {wr, wi, -wi, wr}
__device__ float4 g_cwq4[2][1024];
__device__ float4 g_twq4[2][2744];
__device__ float2 g_cbq [2][64];
__device__ float2 g_tbq [2][196];

typedef unsigned long long u64;

__device__ __forceinline__ u64 pk2(float lo, float hi) {
    u64 r; asm("mov.b64 %0, {%1, %2};" : "=l"(r) : "f"(lo), "f"(hi)); return r;
}
__device__ __forceinline__ void upk2(u64 v, float& lo, float& hi) {
    asm("mov.b64 {%0, %1}, %2;" : "=f"(lo), "=f"(hi) : "l"(v));
}
__device__ __forceinline__ void ffma2(u64& a, u64 x, u64 w) {
    asm("fma.rn.f32x2 %0, %1, %2, %0;" : "+l"(a) : "l"(x), "l"(w));
}
__device__ __forceinline__ void lds2u64(u64& a, u64& b, unsigned addr) {
    asm volatile("ld.shared.v2.u64 {%0, %1}, [%2];" : "=l"(a), "=l"(b) : "r"(addr));
}
__device__ __forceinline__ u64 lds1u64(unsigned addr) {
    u64 r; asm volatile("ld.shared.u64 %0, [%1];" : "=l"(r) : "r"(addr)); return r;
}

// ---------------- K_pack ----------------
__global__ void k_pack(const float* __restrict__ w_lh1, const float* __restrict__ w_lh2,
                       const float* __restrict__ b_lh1, const float* __restrict__ b_lh2,
                       const float* __restrict__ w_t1,  const float* __restrict__ w_t2,
                       const float* __restrict__ b_t1,  const float* __restrict__ b_t2) {
    int i = blockIdx.x * 256 + threadIdx.x;
    if (i < 1024) {
        int n = i >> 8, k = (i >> 4) & 15, d = i & 15;
        int src = n * 256 + d * 16 + k;
        float wr1 = w_lh1[src], wi1 = w_lh1[1024 + src];
        g_cwq4[0][i] = make_float4(wr1, wi1, -wi1, wr1);
        float wr2 = w_lh2[src], wi2 = w_lh2[1024 + src];
        g_cwq4[1][i] = make_float4(wr2, wi2, -wi2, wr2);
    }
    if (i < 2744) {
        int h2 = i / 196, rem = i % 196;
        int k = rem / 14, d = rem % 14;
        int src = (h2 * 14 + d) * 14 + k;
        float wr1 = w_t1[src], wi1 = w_t1[2744 + src];
        g_twq4[0][i] = make_float4(wr1, wi1, -wi1, wr1);
        float wr2 = w_t2[src], wi2 = w_t2[2744 + src];
        g_twq4[1][i] = make_float4(wr2, wi2, -wi2, wr2);
    }
    if (i < 64) {
        g_cbq[0][i] = make_float2(b_lh1[i], b_lh1[64 + i]);
        g_cbq[1][i] = make_float2(b_lh2[i], b_lh2[64 + i]);
    }
    if (i < 196) {
        g_tbq[0][i] = make_float2(b_t1[i], b_t1[196 + i]);
        g_tbq[1][i] = make_float2(b_t2[i], b_t2[196 + i]);
    }
}

// ---------------- K0: transpose x[:, :, 64:128] -> g_img[b][c][hw] ----------------
__global__ void k_transpose_in(const float* __restrict__ x) {
    __shared__ float t[56][65];
    int b   = blockIdx.x / 14;
    int hw0 = (blockIdx.x % 14) * 56;
    #pragma unroll
    for (int it = 0; it < 14; ++it) {
        int idx = it * 256 + threadIdx.x;
        int i = idx >> 6, c = idx & 63;
        t[i][c] = x[((size_t)b * HW + hw0 + i) * NC + CH + c];
    }
    __syncthreads();
    #pragma unroll
    for (int it = 0; it < 14; ++it) {
        int idx = it * 256 + threadIdx.x;
        int i = idx % 56, c = idx / 56;
        g_img[((size_t)b * CH + c) * HW + hw0 + i] = t[i][c];
    }
}

// ---------------- K1: depthwise 3x3 conv ----------------
__global__ void k_dwconv(const float* __restrict__ x, const float* __restrict__ w,
                         const float* __restrict__ bias, float* __restrict__ out) {
    int tid   = threadIdx.x;
    int c     = tid & 63;
    int local = tid >> 6;
    long long base = (long long)blockIdx.x * 4 + local;
    int b  = (int)(base / HW);
    int hw = (int)(base % HW);
    int h  = hw / WW, wc = hw % WW;
    float wr[9];
    #pragma unroll
    for (int j = 0; j < 9; ++j) wr[j] = w[c * 9 + j];
    float acc = bias[c];
    #pragma unroll
    for (int dh = -1; dh <= 1; ++dh) {
        int hh = h + dh;
        if (hh < 0 || hh >= HH) continue;
        #pragma unroll
        for (int dw = -1; dw <= 1; ++dw) {
            int ww2 = wc + dw;
            if (ww2 < 0 || ww2 >= WW) continue;
            acc += x[((size_t)b * HW + hh * WW + ww2) * NC + c] * wr[(dh + 1) * 3 + (dw + 1)];
        }
    }
    out[((size_t)b * HW + hw) * NC + c] = acc;
}

// ---------------- K2: forward DTCWT (warp strip-of-8, R7-best) ----------------
__global__ void __launch_bounds__(128, 7) k_fwd(const float* __restrict__ w_ll) {
    __shared__ __align__(16) float sAp [HH][FP];     // [h][12+w]
    __shared__ __align__(16) float sLoT[WW][FP];     // [w][12+h]
    __shared__ __align__(16) float sHiT[WW][FP];
    __shared__ float sLH[HW], sHL[HW], sHH[HW];

    int bid = blockIdx.x;              // b*64 + c
    int c   = bid & 63;
    int tid = threadIdx.x;
    int ws  = tid >> 5, l = tid & 31;

    for (int i = tid; i < 196; i += 128) {
        float4 v = *(const float4*)(g_img + (size_t)bid * HW + i * 4);
        int h = (i * 4) / 28, w = (i * 4) % 28;
        *(float4*)&sAp[h][12 + w] = v;
    }
    __syncthreads();
    for (int i = tid; i < 28 * 9; i += 128) {
        int h = i / 9, j = i % 9;
        sAp[h][11 - j] = sAp[h][12 + j];
        sAp[h][40 + j] = sAp[h][39 - j];
    }
    __syncthreads();

    if (l < 28) {
        int h = l, w0 = ws * 8;
        float X[32];
        #pragma unroll
        for (int q = 0; q < 8; ++q)
            *(float4*)&X[q * 4] = *(const float4*)&sAp[h][w0 + q * 4];
        #pragma unroll
        for (int t = 0; t < 8; ++t) {
            float hi = 0.f, lo = 0.f;
            #pragma unroll
            for (int j = 0; j < 19; ++j) hi = fmaf(X[3 + t + j], kH1[j], hi);
            #pragma unroll
            for (int j = 0; j < 13; ++j) lo = fmaf(X[6 + t + j], kH0[j], lo);
            if (w0 + t < 28) {
                sLoT[w0 + t][12 + h] = lo;
                sHiT[w0 + t][12 + h] = hi;
            }
        }
    }
    __syncthreads();
    for (int i = tid; i < 28 * 9; i += 128) {
        int w = i / 9, j = i % 9;
        sLoT[w][11 - j] = sLoT[w][12 + j];  sLoT[w][40 + j] = sLoT[w][39 - j];
        sHiT[w][11 - j] = sHiT[w][12 + j];  sHiT[w][40 + j] = sHiT[w][39 - j];
    }
    __syncthreads();

    if (l < 28) {
        int w = l, h0 = ws * 8;
        float ll[8], lh[8];
        {
            float Y[32];
            #pragma unroll
            for (int q = 0; q < 8; ++q)
                *(float4*)&Y[q * 4] = *(const float4*)&sLoT[w][h0 + q * 4];
            #pragma unroll
            for (int t = 0; t < 8; ++t) {
                float a = 0.f, b2 = 0.f;
                #pragma unroll
                for (int j = 0; j < 13; ++j) a = fmaf(Y[6 + t + j], kH0[j], a);
                #pragma unroll
                for (int j = 0; j < 19; ++j) b2 = fmaf(Y[3 + t + j], kH1[j], b2);
                ll[t] = a; lh[t] = b2;
            }
        }
        float hl[8], hh[8];
        {
            float Z[32];
            #pragma unroll
            for (int q = 0; q < 8; ++q)
                *(float4*)&Z[q * 4] = *(const float4*)&sHiT[w][h0 + q * 4];
            #pragma unroll
            for (int t = 0; t < 8; ++t) {
                float a = 0.f, b2 = 0.f;
                #pragma unroll
                for (int j = 0; j < 13; ++j) a = fmaf(Z[6 + t + j], kH0[j], a);
                #pragma unroll
                for (int j = 0; j < 19; ++j) b2 = fmaf(Z[3 + t + j], kH1[j], b2);
                hl[t] = a; hh[t] = b2;
            }
        }
        #pragma unroll
        for (int t = 0; t < 8; ++t) {
            if (h0 + t < 28) {
                int pos = (h0 + t) * 28 + w;
                g_ll[(size_t)bid * HW + pos] = ll[t] * w_ll[c * HW + pos];
                sLH[pos] = lh[t]; sHL[pos] = hl[t]; sHH[pos] = hh[t];
            }
        }
    }
    __syncthreads();

    for (int p = tid; p < 196; p += 128) {
        int h2 = p / 14, w2 = p - h2 * 14;
        int o  = (2 * h2) * WW + 2 * w2;
        #pragma unroll
        for (int band = 0; band < 3; ++band) {
            const float* src = (band == 0) ? sLH : (band == 1) ? sHH : sHL;
            int sp = (band == 0) ? 0 : (band == 1) ? 1 : 2;
            int sq = (band == 0) ? 5 : (band == 1) ? 4 : 3;
            float a  = src[o]          * INV_SQRT2;
            float bb = src[o + 1]      * INV_SQRT2;
            float cc = src[o + WW]     * INV_SQRT2;
            float dd = src[o + WW + 1] * INV_SQRT2;
            size_t bp = ((size_t)bid * 6 + sp) * P2 + p;
            size_t bq = ((size_t)bid * 6 + sq) * P2 + p;
            g_xh[0][bp] = a - dd;
            g_xh[1][bp] = bb + cc;
            g_xh[0][bq] = a + dd;
            g_xh[1][bq] = bb - cc;
        }
    }
}

// ---------------- K3a: channel mixing (R5-best) ----------------
__global__ void __launch_bounds__(256, 2) k_chmix() {
    __shared__ float4 scw[2][1024];
    __shared__ float2 scb[2][64];
    int tid = threadIdx.x;
    #pragma unroll
    for (int i = 0; i < 4; ++i) {
        scw[0][tid + 256 * i] = g_cwq4[0][tid + 256 * i];
        scw[1][tid + 256 * i] = g_cwq4[1][tid + 256 * i];
    }
    if (tid < 64) { scb[0][tid] = g_cbq[0][tid]; scb[1][tid] = g_cbq[1][tid]; }
    __syncthreads();

    unsigned w0a = (unsigned)__cvta_generic_to_shared(&scw[0][0]);
    unsigned w1a = (unsigned)__cvta_generic_to_shared(&scw[1][0]);
    unsigned b0a = (unsigned)__cvta_generic_to_shared(&scb[0][0]);
    unsigned b1a = (unsigned)__cvta_generic_to_shared(&scb[1][0]);

    int item = blockIdx.x * 256 + tid;
    int b = item / 1176, rem = item - b * 1176;
    int s = rem / 196, p = rem - s * 196;
    float* Xr = g_xh[0];
    float* Xi = g_xh[1];
    size_t base = ((size_t)b * 384 + s) * 196 + p;

    for (int n = 0; n < 4; ++n) {
        u64 Xp[16], Xq[16];
        #pragma unroll
        for (int d = 0; d < 16; ++d) {
            float r = Xr[base + (size_t)(n * 16 + d) * 1176];
            float m = Xi[base + (size_t)(n * 16 + d) * 1176];
            Xp[d] = pk2(r, r);
            Xq[d] = pk2(m, m);
        }
        float mr[16], mi[16];
        #pragma unroll
        for (int k = 0; k < 16; ++k) {
            u64 A = lds1u64(b0a + (unsigned)(n * 16 + k) * 8);
            unsigned wa = w0a + (unsigned)((n * 16 + k) * 16) * 16;
            #pragma unroll
            for (int d = 0; d < 16; ++d) {
                u64 W0, W1; lds2u64(W0, W1, wa + d * 16);
                ffma2(A, Xp[d], W0);
                ffma2(A, Xq[d], W1);
            }
            float ar, ai; upk2(A, ar, ai);
            mr[k] = fmaxf(ar, 0.f);
            mi[k] = fmaxf(ai, 0.f);
        }
        #pragma unroll
        for (int d = 0; d < 16; ++d) { Xp[d] = pk2(mr[d], mr[d]); Xq[d] = pk2(mi[d], mi[d]); }
        #pragma unroll
        for (int k = 0; k < 16; ++k) {
            u64 A = lds1u64(b1a + (unsigned)(n * 16 + k) * 8);
            unsigned wa = w1a + (unsigned)((n * 16 + k) * 16) * 16;
            #pragma unroll
            for (int d = 0; d < 16; ++d) {
                u64 W0, W1; lds2u64(W0, W1, wa + d * 16);
                ffma2(A, Xp[d], W0);
                ffma2(A, Xq[d], W1);
            }
            float ar, ai; upk2(A, ar, ai);
            Xr[base + (size_t)(n * 16 + k) * 1176] = ar;
            Xi[base + (size_t)(n * 16 + k) * 1176] = ai;
        }
    }
}

// ---------------- K3b: token mixing (R5-best) ----------------
__global__ void __launch_bounds__(128, 4) k_token() {
    __shared__ float4 stw[2][196];
    __shared__ float2 stb[2][14];
    int tid = threadIdx.x;
    int b  = blockIdx.x / 42;
    int r  = blockIdx.x % 42;
    int h2 = r / 3;
    int gs = r % 3;
    for (int i = tid; i < 196; i += 128) {
        stw[0][i] = g_twq4[0][h2 * 196 + i];
        stw[1][i] = g_twq4[1][h2 * 196 + i];
    }
    if (tid < 14) { stb[0][tid] = g_tbq[0][h2 * 14 + tid]; stb[1][tid] = g_tbq[1][h2 * 14 + tid]; }
    __syncthreads();

    unsigned w0a = (unsigned)__cvta_generic_to_shared(&stw[0][0]);
    unsigned w1a = (unsigned)__cvta_generic_to_shared(&stw[1][0]);
    unsigned b0a = (unsigned)__cvta_generic_to_shared(&stb[0][0]);
    unsigned b1a = (unsigned)__cvta_generic_to_shared(&stb[1][0]);

    int s = gs * 2 + (tid >> 6);
    int c = tid & 63;
    size_t base = ((size_t)(b * 64 + c) * 6 + s) * 196 + h2 * 14;
    float2* Rp = (float2*)(g_xh[0] + base);
    float2* Ip = (float2*)(g_xh[1] + base);

    u64 Xp[14], Xq[14];
    #pragma unroll
    for (int j = 0; j < 7; ++j) {
        float2 v = Rp[j];
        Xp[2 * j]     = pk2(v.x, v.x);
        Xp[2 * j + 1] = pk2(v.y, v.y);
        float2 w = Ip[j];
        Xq[2 * j]     = pk2(w.x, w.x);
        Xq[2 * j + 1] = pk2(w.y, w.y);
    }
    float mr[14], mi[14];
    #pragma unroll
    for (int k = 0; k < 14; ++k) {
        u64 A = lds1u64(b0a + (unsigned)k * 8);
        unsigned wa = w0a + (unsigned)(k * 14) * 16;
        #pragma unroll
        for (int d = 0; d < 14; ++d) {
            u64 W0, W1; lds2u64(W0, W1, wa + d * 16);
            ffma2(A, Xp[d], W0);
            ffma2(A, Xq[d], W1);
        }
        float ar, ai; upk2(A, ar, ai);
        mr[k] = fmaxf(ar, 0.f);
        mi[k] = fmaxf(ai, 0.f);
    }
    #pragma unroll
    for (int d = 0; d < 14; ++d) { Xp[d] = pk2(mr[d], mr[d]); Xq[d] = pk2(mi[d], mi[d]); }
    float outr[14], outi[14];
    #pragma unroll
    for (int k = 0; k < 14; ++k) {
        u64 A = lds1u64(b1a + (unsigned)k * 8);
        unsigned wa = w1a + (unsigned)(k * 14) * 16;
        #pragma unroll
        for (int d = 0; d < 14; ++d) {
            u64 W0, W1; lds2u64(W0, W1, wa + d * 16);
            ffma2(A, Xp[d], W0);
            ffma2(A, Xq[d], W1);
        }
        upk2(A, outr[k], outi[k]);
    }
    #pragma unroll
    for (int j = 0; j < 7; ++j) {
        Rp[j] = make_float2(outr[2 * j], outr[2 * j + 1]);
        Ip[j] = make_float2(outi[2 * j], outi[2 * j + 1]);
    }
}

// ---------------- K4: inverse DTCWT (strip-of-4, pad-9, R5-best) ----------------
__global__ void __launch_bounds__(224, 2) k_inv() {
    __shared__ float sLLT[WW][CP];     // transposed padded (pad in h)
    __shared__ float sLHT[WW][CP];
    __shared__ float sHLT[WW][CP];
    __shared__ float sHHT[WW][CP];
    __shared__ float sLo [HH][CP];     // row-major padded (pad in w)
    __shared__ float sHi [HH][CP];

    int bid = blockIdx.x;
    int tid = threadIdx.x;

    if (tid < 196) {
        float4 v = *(const float4*)(g_ll + (size_t)bid * HW + tid * 4);
        int h = (tid * 4) / 28, w = (tid * 4) % 28;
        sLLT[w][9 + h]     = v.x;
        sLLT[w + 1][9 + h] = v.y;
        sLLT[w + 2][9 + h] = v.z;
        sLLT[w + 3][9 + h] = v.w;
    }

    if (tid < 196) {   // c2q -> transposed arrays
        int p = tid, h2 = p / 14, w2 = p - h2 * 14;
        size_t base = (size_t)bid * 6 * P2;
        int hr = 9 + 2 * h2, wc = 2 * w2;
        #pragma unroll
        for (int band = 0; band < 3; ++band) {
            int sa = (band == 0) ? 0 : (band == 1) ? 2 : 1;   // lh:(0,5) hl:(2,3) hh:(1,4)
            int sb = (band == 0) ? 5 : (band == 1) ? 3 : 4;
            float ra = g_xh[0][base + sa * P2 + p], ia = g_xh[1][base + sa * P2 + p];
            float rb = g_xh[0][base + sb * P2 + p], ib = g_xh[1][base + sb * P2 + p];
            float (*dst)[CP] = (band == 0) ? sLHT : (band == 1) ? sHLT : sHHT;
            dst[wc][hr]         = (ra + rb) * INV_SQRT2;
            dst[wc + 1][hr]     = (ia + ib) * INV_SQRT2;
            dst[wc][hr + 1]     = (ia - ib) * INV_SQRT2;
            dst[wc + 1][hr + 1] = (rb - ra) * INV_SQRT2;
        }
    }
    __syncthreads();
    for (int i = tid; i < 28 * 9; i += 224) {
        int w = i / 9, j = i % 9;
        sLLT[w][8 - j] = sLLT[w][9 + j];  sLLT[w][37 + j] = sLLT[w][36 - j];
        sLHT[w][8 - j] = sLHT[w][9 + j];  sLHT[w][37 + j] = sLHT[w][36 - j];
        sHLT[w][8 - j] = sHLT[w][9 + j];  sHLT[w][37 + j] = sHLT[w][36 - j];
        sHHT[w][8 - j] = sHHT[w][9 + j];  sHHT[w][37 + j] = sHHT[w][36 - j];
    }
    __syncthreads();

    if (tid < 196) {
        int w = tid % 28, h0 = (tid / 28) * 4;
        {
            float A[22], B[22];
            #pragma unroll
            for (int j = 0; j < 22; ++j) A[j] = sLLT[w][h0 + j];
            #pragma unroll
            for (int j = 0; j < 22; ++j) B[j] = sLHT[w][h0 + j];
            #pragma unroll
            for (int t = 0; t < 4; ++t) {
                float lo = 0.f;
                #pragma unroll
                for (int j = 0; j < 19; ++j) lo = fmaf(A[t + j], kG0[j], lo);
                #pragma unroll
                for (int j = 0; j < 13; ++j) lo = fmaf(B[t + 3 + j], kG1[j], lo);
                sLo[h0 + t][9 + w] = lo;
            }
        }
        {
            float A[22], B[22];
            #pragma unroll
            for (int j = 0; j < 22; ++j) A[j] = sHLT[w][h0 + j];
            #pragma unroll
            for (int j = 0; j < 22; ++j) B[j] = sHHT[w][h0 + j];
            #pragma unroll
            for (int t = 0; t < 4; ++t) {
                float hi = 0.f;
                #pragma unroll
                for (int j = 0; j < 19; ++j) hi = fmaf(A[t + j], kG0[j], hi);
                #pragma unroll
                for (int j = 0; j < 13; ++j) hi = fmaf(B[t + 3 + j], kG1[j], hi);
                sHi[h0 + t][9 + w] = hi;
            }
        }
    }
    __syncthreads();
    for (int i = tid; i < 28 * 9; i += 224) {
        int h = i / 9, j = i % 9;
        sLo[h][8 - j] = sLo[h][9 + j];  sLo[h][37 + j] = sLo[h][36 - j];
        sHi[h][8 - j] = sHi[h][9 + j];  sHi[h][37 + j] = sHi[h][36 - j];
    }
    __syncthreads();

    if (tid < 196) {
        int h = tid % 28, w0 = (tid / 28) * 4;
        float X[22], Y[22];
        #pragma unroll
        for (int j = 0; j < 22; ++j) X[j] = sLo[h][w0 + j];
        #pragma unroll
        for (int j = 0; j < 22; ++j) Y[j] = sHi[h][w0 + j];
        float4 v;
        float o[4];
        #pragma unroll
        for (int t = 0; t < 4; ++t) {
            float r = 0.f;
            #pragma unroll
            for (int j = 0; j < 19; ++j) r = fmaf(X[t + j], kG0[j], r);
            #pragma unroll
            for (int j = 0; j < 13; ++j) r = fmaf(Y[t + 3 + j], kG1[j], r);
            o[t] = r;
        }
        v.x = o[0]; v.y = o[1]; v.z = o[2]; v.w = o[3];
        *(float4*)(g_img + (size_t)bid * HW + h * 28 + w0) = v;
    }
}

// ---------------- K5: transpose g_img -> out[:, :, 64:128] ----------------
__global__ void k_transpose_out(float* __restrict__ out) {
    __shared__ float t[56][65];
    int b   = blockIdx.x / 14;
    int hw0 = (blockIdx.x % 14) * 56;
    #pragma unroll
    for (int it = 0; it < 14; ++it) {
        int idx = it * 256 + threadIdx.x;
        int i = idx % 56, c = idx / 56;
        t[i][c] = g_img[((size_t)b * CH + c) * HW + hw0 + i];
    }
    __syncthreads();
    #pragma unroll
    for (int it = 0; it < 14; ++it) {
        int idx = it * 256 + threadIdx.x;
        int i = idx >> 6, c = idx & 63;
        out[((size_t)b * HW + hw0 + i) * NC + CH + c] = t[i][c];
    }
}

extern "C" void kernel_launch(void* const* d_in, const int* in_sizes, int n_in,
                              void* d_out, int out_size) {
    const float* x      = (const float*)d_in[0];
    const float* conv_w = (const float*)d_in[1];
    const float* conv_b = (const float*)d_in[2];
    const float* w_ll   = (const float*)d_in[3];
    const float* w_lh1  = (const float*)d_in[4];
    const float* w_lh2  = (const float*)d_in[5];
    const float* b_lh1  = (const float*)d_in[6];
    const float* b_lh2  = (const float*)d_in[7];
    const float* w_t1   = (const float*)d_in[8];
    const float* w_t2   = (const float*)d_in[9];
    const float* b_t1   = (const float*)d_in[10];
    const float* b_t2   = (const float*)d_in[11];
    float* out = (float*)d_out;

    k_pack<<<11, 256>>>(w_lh1, w_lh2, b_lh1, b_lh2, w_t1, w_t2, b_t1, b_t2);
    k_transpose_in<<<BB * 14, 256>>>(x);
    k_dwconv<<<BB * HW / 4, 256>>>(x, conv_w, conv_b, out);
    k_fwd<<<BB * CH, 128>>>(w_ll);
    k_chmix<<<1176, 256>>>();
    k_token<<<BB * 14 * 3, 128>>>();
    k_inv<<<BB * CH, 224>>>();
    k_transpose_out<<<BB * 14, 256>>>(out);
}